// round 5
// baseline (speedup 1.0000x reference)
#include <cuda_runtime.h>
#include <math.h>

#define BATCH 8192
#define EDIM  1024
#define DIN   384
#define HID   64
#define NR    8
#define NGATEBLK (BATCH/8)

// ---------------- scratch (module-load allocated; no runtime allocs) -------
__device__ float g_ev [EDIM*NR*HID];        // [e][r][h], l2-normalized (2MB)
__device__ float g_xu [BATCH*2*HID];        // [pair][h], l2-normalized (4MB)
__device__ float g_esc[BATCH*2*EDIM];       // exp(score) per pair (64MB)
__device__ float g_Z  [BATCH*2];            // sum of exp per pair
__device__ int   g_top2[BATCH*2];           // router id per (sample,k)
__device__ float g_gw [BATCH*2];            // gate weight per (sample,k)
__device__ int   g_cnt[NR];                 // bucket counts
__device__ int   g_list[NR][BATCH];         // pair ids bucketed by router
__device__ float g_psum[NGATEBLK][NR];      // per-block prob sums (aux)
__device__ float g_msum[NGATEBLK][NR];      // per-block mask sums (aux)

// ---------------- K0: zero bucket counts -----------------------------------
__global__ void k_zero() {
    int t = threadIdx.x;
    if (t < NR) g_cnt[t] = 0;
}

// ---------------- K1: gate (logits, softmax, top2, buckets, aux partials) --
__global__ void __launch_bounds__(256) k_gate(const float* __restrict__ x,
                                              const float* __restrict__ gw,
                                              const float* __restrict__ gb) {
    __shared__ float s_gw[DIN*NR];          // 12KB
    __shared__ float s_pw[8][NR];
    __shared__ int   s_iw[8][2];
    int t = threadIdx.x;
    for (int q = t; q < DIN*NR/4; q += 256)
        ((float4*)s_gw)[q] = ((const float4*)gw)[q];
    __syncthreads();

    int warp = t >> 5, lane = t & 31;
    int b = blockIdx.x*8 + warp;
    float a[NR];
    #pragma unroll
    for (int r = 0; r < NR; r++) a[r] = 0.f;
    for (int d = lane; d < DIN; d += 32) {
        float xv = x[b*DIN + d];
        #pragma unroll
        for (int r = 0; r < NR; r++) a[r] = fmaf(xv, s_gw[d*NR + r], a[r]);
    }
    #pragma unroll
    for (int r = 0; r < NR; r++) {
        #pragma unroll
        for (int off = 16; off > 0; off >>= 1)
            a[r] += __shfl_down_sync(0xffffffffu, a[r], off);
    }
    if (lane == 0) {
        float l[NR];
        #pragma unroll
        for (int r = 0; r < NR; r++) l[r] = a[r] + gb[r];
        float m = l[0];
        #pragma unroll
        for (int r = 1; r < NR; r++) m = fmaxf(m, l[r]);
        float p[NR]; float Zs = 0.f;
        #pragma unroll
        for (int r = 0; r < NR; r++) { p[r] = expf(l[r] - m); Zs += p[r]; }
        float iZ = 1.f/Zs;
        #pragma unroll
        for (int r = 0; r < NR; r++) p[r] *= iZ;
        // top-2 with lax.top_k tie rule (lowest index wins) via strict >
        int i0 = 0; float v0 = l[0];
        #pragma unroll
        for (int r = 1; r < NR; r++) if (l[r] > v0) { v0 = l[r]; i0 = r; }
        int i1 = -1; float v1 = -INFINITY;
        #pragma unroll
        for (int r = 0; r < NR; r++) if (r != i0 && l[r] > v1) { v1 = l[r]; i1 = r; }
        float e1 = expf(v1 - v0);
        float wd = 1.f + e1;
        g_top2[2*b]   = i0; g_top2[2*b+1] = i1;
        g_gw[2*b]     = 1.f/wd; g_gw[2*b+1] = e1/wd;
        int p0 = atomicAdd(&g_cnt[i0], 1); g_list[i0][p0] = 2*b;
        int p1 = atomicAdd(&g_cnt[i1], 1); g_list[i1][p1] = 2*b + 1;
        #pragma unroll
        for (int r = 0; r < NR; r++) s_pw[warp][r] = p[r];
        s_iw[warp][0] = i0; s_iw[warp][1] = i1;
    }
    __syncthreads();
    if (t < NR) {  // deterministic per-block reduction (fixed order)
        float ps = 0.f, ms = 0.f;
        #pragma unroll
        for (int w = 0; w < 8; w++) {
            ps += s_pw[w][t];
            ms += (s_iw[w][0] == t ? 1.f : 0.f) + (s_iw[w][1] == t ? 1.f : 0.f);
        }
        g_psum[blockIdx.x][t] = ps;
        g_msum[blockIdx.x][t] = ms;
    }
}

// ---------------- K1b: aux loss finalize ------------------------------------
__global__ void __launch_bounds__(256) k_aux(float* __restrict__ out) {
    __shared__ float red[256];
    int t = threadIdx.x;
    float pr[NR], mr[NR];
    #pragma unroll
    for (int r = 0; r < NR; r++) { pr[r] = 0.f; mr[r] = 0.f; }
    for (int blk = t; blk < NGATEBLK; blk += 256) {
        #pragma unroll
        for (int r = 0; r < NR; r++) {
            pr[r] += g_psum[blk][r];
            mr[r] += g_msum[blk][r];
        }
    }
    float aux = 0.f;
    for (int r = 0; r < NR; r++) {
        red[t] = pr[r]; __syncthreads();
        for (int s = 128; s > 0; s >>= 1) { if (t < s) red[t] += red[t+s]; __syncthreads(); }
        float P = red[0]; __syncthreads();
        red[t] = mr[r]; __syncthreads();
        for (int s = 128; s > 0; s >>= 1) { if (t < s) red[t] += red[t+s]; __syncthreads(); }
        float M = red[0]; __syncthreads();
        aux += (P/(float)BATCH) * (M/(float)BATCH);
    }
    if (t == 0) out[2*BATCH] = (float)NR * aux * 0.05f;
}

// ---------------- K2: ev = l2norm(re @ Vw[r] + Vb[r]) -----------------------
__global__ void __launch_bounds__(256) k_ev(const float* __restrict__ re,
                                            const float* __restrict__ Vw,
                                            const float* __restrict__ Vb) {
    __shared__ float s_x[16*DIN];           // 24KB
    __shared__ float s_y[16*HID];           // 4KB
    __shared__ float s_sc[16];
    int t = threadIdx.x;
    int r = blockIdx.y;
    int e0 = blockIdx.x * 16;
    for (int q = t; q < 16*DIN/4; q += 256)
        ((float4*)s_x)[q] = ((const float4*)(re + (size_t)e0*DIN))[q];
    __syncthreads();
    int h = t & 63, sg = t >> 6;
    float acc[4] = {0.f,0.f,0.f,0.f};
    const float* Vwr = Vw + r*DIN*HID;
    for (int d = 0; d < DIN; d += 4) {
        float u0 = Vwr[(d+0)*HID + h];
        float u1 = Vwr[(d+1)*HID + h];
        float u2 = Vwr[(d+2)*HID + h];
        float u3 = Vwr[(d+3)*HID + h];
        #pragma unroll
        for (int j = 0; j < 4; j++) {
            float4 xv = *(const float4*)&s_x[(sg*4+j)*DIN + d];
            acc[j] = fmaf(xv.x,u0, fmaf(xv.y,u1, fmaf(xv.z,u2, fmaf(xv.w,u3, acc[j]))));
        }
    }
    float bv = Vb[r*HID + h];
    #pragma unroll
    for (int j = 0; j < 4; j++) s_y[(sg*4+j)*HID + h] = acc[j] + bv;
    __syncthreads();
    if (t < 16) {
        float ss = 0.f;
        for (int k = 0; k < HID; k++) { float v = s_y[t*HID+k]; ss = fmaf(v, v, ss); }
        s_sc[t] = 1.f / fmaxf(sqrtf(ss), 1e-12f);
    }
    __syncthreads();
    #pragma unroll
    for (int j = 0; j < 4; j++) {
        int el = sg*4 + j;
        g_ev[((size_t)(e0+el)*NR + r)*HID + h] = s_y[el*HID + h] * s_sc[el];
    }
}

// ---------------- K3: xu for selected (sample,k) pairs, bucketed by router --
__global__ void __launch_bounds__(256) k_xu(const float* __restrict__ x,
                                            const float* __restrict__ Uw,
                                            const float* __restrict__ Ub) {
    int r = blockIdx.y;
    int base = blockIdx.x * 16;
    int cnt = g_cnt[r];
    if (base >= cnt) return;
    __shared__ int   s_pid[16];
    __shared__ float s_x[16*DIN];           // 24KB
    __shared__ float s_y[16*HID];
    __shared__ float s_sc[16];
    int t = threadIdx.x;
    if (t < 16) {
        int idx = base + t;
        s_pid[t] = g_list[r][(idx < cnt) ? idx : base];
    }
    __syncthreads();
    for (int q = t; q < 16*96; q += 256) {  // 16 rows * 96 float4
        int row = q / 96, c4 = q % 96;
        ((float4*)s_x)[q] = *(const float4*)&x[(size_t)(s_pid[row] >> 1)*DIN + c4*4];
    }
    __syncthreads();
    int h = t & 63, sg = t >> 6;
    float acc[4] = {0.f,0.f,0.f,0.f};
    const float* Uwr = Uw + r*DIN*HID;
    for (int d = 0; d < DIN; d += 4) {
        float u0 = Uwr[(d+0)*HID + h];
        float u1 = Uwr[(d+1)*HID + h];
        float u2 = Uwr[(d+2)*HID + h];
        float u3 = Uwr[(d+3)*HID + h];
        #pragma unroll
        for (int j = 0; j < 4; j++) {
            float4 xv = *(const float4*)&s_x[(sg*4+j)*DIN + d];
            acc[j] = fmaf(xv.x,u0, fmaf(xv.y,u1, fmaf(xv.z,u2, fmaf(xv.w,u3, acc[j]))));
        }
    }
    float bv = Ub[r*HID + h];
    #pragma unroll
    for (int j = 0; j < 4; j++) s_y[(sg*4+j)*HID + h] = acc[j] + bv;
    __syncthreads();
    if (t < 16) {
        float ss = 0.f;
        for (int k = 0; k < HID; k++) { float v = s_y[t*HID+k]; ss = fmaf(v, v, ss); }
        s_sc[t] = 1.f / fmaxf(sqrtf(ss), 1e-12f);
    }
    __syncthreads();
    #pragma unroll
    for (int j = 0; j < 4; j++) {
        int el = sg*4 + j;
        if (base + el < cnt)
            g_xu[(size_t)s_pid[el]*HID + h] = s_y[el*HID + h] * s_sc[el];
    }
}

// ---------------- K4: scores + exp + Z (xu in regs, ev tiles in smem) -------
__global__ void __launch_bounds__(256, 2) k_scores() {
    __shared__ float s_ev[16*NR*68];        // 34816B, H padded 64->68 (bank-safe)
    __shared__ float s_es[64*17];           // 4352B exp staging, pad 17
    __shared__ float s_zr[256];
    int t = threadIdx.x;
    int c = blockIdx.x;                     // 32 samples -> 64 pairs per CTA
    int p = t & 63, eg = t >> 6;
    int pair = c*64 + p;
    int r = g_top2[pair];
    float4 xr[16];
    #pragma unroll
    for (int q = 0; q < 16; q++) xr[q] = *(const float4*)&g_xu[(size_t)pair*HID + q*4];

    float Zacc = 0.f;
    for (int et = 0; et < EDIM/16; et++) {
        int e0 = et*16;
        __syncthreads();
        const float4* gsrc = (const float4*)&g_ev[(size_t)e0*NR*HID];
        #pragma unroll
        for (int i = 0; i < 8; i++) {
            int q = t + 256*i;              // 2048 float4
            int e_l = q >> 7, rem = q & 127, r_l = rem >> 4, h4 = rem & 15;
            *(float4*)&s_ev[(e_l*NR + r_l)*68 + h4*4] = gsrc[q];
        }
        __syncthreads();
        float acc0=0.f, acc1=0.f, acc2=0.f, acc3=0.f;
        const float* b0 = &s_ev[((eg*4+0)*NR + r)*68];
        const float* b1 = b0 + NR*68;
        const float* b2 = b1 + NR*68;
        const float* b3 = b2 + NR*68;
        #pragma unroll
        for (int q = 0; q < 16; q++) {
            float4 xv = xr[q];
            float4 a4 = *(const float4*)(b0 + q*4);
            float4 c4 = *(const float4*)(b1 + q*4);
            float4 d4 = *(const float4*)(b2 + q*4);
            float4 e4 = *(const float4*)(b3 + q*4);
            acc0 = fmaf(xv.x,a4.x,fmaf(xv.y,a4.y,fmaf(xv.z,a4.z,fmaf(xv.w,a4.w,acc0))));
            acc1 = fmaf(xv.x,c4.x,fmaf(xv.y,c4.y,fmaf(xv.z,c4.z,fmaf(xv.w,c4.w,acc1))));
            acc2 = fmaf(xv.x,d4.x,fmaf(xv.y,d4.y,fmaf(xv.z,d4.z,fmaf(xv.w,d4.w,acc2))));
            acc3 = fmaf(xv.x,e4.x,fmaf(xv.y,e4.y,fmaf(xv.z,e4.z,fmaf(xv.w,e4.w,acc3))));
        }
        // scores bounded in [-1,1] (both operands unit-norm): exp w/o max-sub
        float es0 = __expf(acc0), es1 = __expf(acc1), es2 = __expf(acc2), es3 = __expf(acc3);
        Zacc += es0 + es1 + es2 + es3;
        s_es[p*17 + eg*4+0] = es0;
        s_es[p*17 + eg*4+1] = es1;
        s_es[p*17 + eg*4+2] = es2;
        s_es[p*17 + eg*4+3] = es3;
        __syncthreads();
        #pragma unroll
        for (int i = 0; i < 4; i++) {       // coalesced spill of 64x16 exp tile
            int o = t + 256*i;
            int row = o >> 4, e = o & 15;
            g_esc[(size_t)(c*64 + row)*EDIM + e0 + e] = s_es[row*17 + e];
        }
    }
    s_zr[t] = Zacc;
    __syncthreads();
    if (t < 64)
        g_Z[c*64 + t] = s_zr[t] + s_zr[64 + t] + s_zr[128 + t] + s_zr[192 + t];
}

// ---------------- K5: combine, inverse-CDF sample, log-prob -----------------
__global__ void __launch_bounds__(256) k_sample(const float* __restrict__ rnd_in,
                                                float* __restrict__ out) {
    int t = threadIdx.x;
    int warp = t >> 5, lane = t & 31;
    int b = blockIdx.x*8 + warp;
    float f0 = g_gw[2*b]   / g_Z[2*b];
    float f1 = g_gw[2*b+1] / g_Z[2*b+1];
    const float* e0p = &g_esc[(size_t)(2*b)*EDIM];
    const float* e1p = e0p + EDIM;
    float rnd = rnd_in[b];
    float base = 0.f;
    int sel = -1; float psel = 0.f;
    for (int s = 0; s < EDIM/32; s++) {
        int e = s*32 + lane;
        float pv = fmaf(e0p[e], f0, e1p[e]*f1);
        float sc = pv;
        #pragma unroll
        for (int off = 1; off < 32; off <<= 1) {
            float v = __shfl_up_sync(0xffffffffu, sc, off);
            if (lane >= off) sc += v;
        }
        float cum = base + sc;
        unsigned m = __ballot_sync(0xffffffffu, cum > rnd);
        if (m) {
            int l = __ffs(m) - 1;
            sel = s*32 + l;
            psel = __shfl_sync(0xffffffffu, pv, l);
            break;
        }
        base += __shfl_sync(0xffffffffu, sc, 31);
    }
    if (sel < 0) {  // jnp.argmax of all-False -> 0
        sel = 0;
        psel = fmaf(e0p[0], f0, e1p[0]*f1);
    }
    if (lane == 0) {
        out[b]         = (float)sel;
        out[BATCH + b] = logf(psel);
    }
}

// ---------------- launch -----------------------------------------------------
extern "C" void kernel_launch(void* const* d_in, const int* in_sizes, int n_in,
                              void* d_out, int out_size) {
    (void)in_sizes; (void)n_in; (void)out_size;
    const float* x   = (const float*)d_in[0];
    const float* re  = (const float*)d_in[1];
    const float* rnd = (const float*)d_in[2];
    const float* gw  = (const float*)d_in[3];
    const float* gb  = (const float*)d_in[4];
    const float* Uw  = (const float*)d_in[5];
    const float* Ub  = (const float*)d_in[6];
    const float* Vw  = (const float*)d_in[7];
    const float* Vb  = (const float*)d_in[8];
    float* out = (float*)d_out;

    k_zero  <<<1, 32>>>();
    k_gate  <<<NGATEBLK, 256>>>(x, gw, gb);
    k_aux   <<<1, 256>>>(out);
    k_ev    <<<dim3(EDIM/16, NR), 256>>>(re, Vw, Vb);
    k_xu    <<<dim3(BATCH/16, NR), 256>>>(x, Uw, Ub);
    k_scores<<<BATCH/32, 256>>>();
    k_sample<<<BATCH/8, 256>>>(rnd, out);
}